// round 15
// baseline (speedup 1.0000x reference)
#include <cuda_runtime.h>
#include <cstdint>

// convection_vectors: (N_NODES, 3) float32      -> d_in[0]
// mesh_elements:      (E, 4)       int32        -> d_in[1]
// inv_matrices:       (E, 4, 4)    float32      -> d_in[2]
// out:                (E, 4, 3)    float32      -> d_out
//
// out[e,i,c] = sum_j inv[e,i,j] * conv[mesh[e,j], c]

#define MAX_NODES 400000

// Padded gather table: (N, 4) so each vertex is one aligned 16B load. 6.4 MB -> L2-resident.
__device__ float4 g_conv4[MAX_NODES];

// Monotonic ticket counter for the reset-free grid barrier (zero-initialized,
// never reset: each launch consumes exactly gridDim.x tickets; a CTA's ticket
// value determines its epoch target, so replays need no counter reset).
__device__ unsigned long long g_ticket;

__device__ __forceinline__ uint32_t smem_u32(const void* p)
{
    uint32_t a;
    asm("{ .reg .u64 t; cvta.to.shared.u64 t, %1; cvt.u32.u64 %0, t; }" : "=r"(a) : "l"(p));
    return a;
}

// Fused persistent kernel (R11 retry with the two identified bugs fixed):
//  - __launch_bounds__(256, 8): regs capped at 32 -> 8 CTAs/SM co-resident.
//  - 4 smem tile buffers with LAZY TMA drain: commit with no wait; before
//    reusing buffer (it&3) (it>=4), wait_group 3 drains exactly the group
//    that consumed this buffer 4 tiles ago. No per-tile synchronous drain.
__global__ void __launch_bounds__(256, 8)
fem_fused_kernel(const float*  __restrict__ conv,
                 const int4*   __restrict__ elems,
                 const float4* __restrict__ inv,
                 float*        __restrict__ out,
                 int n_nodes,
                 int total_rows)   // 4*E
{
    __shared__ __align__(16) float s_out[4][256 * 3];   // 4 x 3 KB tiles

    const int tile_rows = 256;
    const int grid = gridDim.x;

    // ---- Phase 1: cooperative pad (groups of 4 nodes, fully coalesced) ----
    {
        const float4* conv4 = (const float4*)conv;
        int n_groups = n_nodes >> 2;
        int gtid = blockIdx.x * blockDim.x + threadIdx.x;
        int nthreads = grid * blockDim.x;
        for (int j = gtid; j < n_groups; j += nthreads) {
            float4 c0 = __ldg(&conv4[j * 3 + 0]);
            float4 c1 = __ldg(&conv4[j * 3 + 1]);
            float4 c2 = __ldg(&conv4[j * 3 + 2]);
            int base = j * 4;
            g_conv4[base + 0] = make_float4(c0.x, c0.y, c0.z, 0.0f);
            g_conv4[base + 1] = make_float4(c0.w, c1.x, c1.y, 0.0f);
            g_conv4[base + 2] = make_float4(c1.z, c1.w, c2.x, 0.0f);
            g_conv4[base + 3] = make_float4(c2.y, c2.z, c2.w, 0.0f);
        }
        if (gtid == 0) {
            for (int i = n_groups * 4; i < n_nodes; i++) {
                long b = (long)i * 3;
                g_conv4[i] = make_float4(conv[b], conv[b + 1], conv[b + 2], 0.0f);
            }
        }
    }

    // ---- Reset-free grid barrier (all CTAs co-resident by launch bounds) ----
    {
        __syncthreads();
        if (threadIdx.x == 0) {
            __threadfence();
            unsigned long long tkt = atomicAdd(&g_ticket, 1ULL) + 1ULL;
            unsigned long long target = ((tkt + grid - 1ULL) / grid) * grid;
            while (*(volatile unsigned long long*)&g_ticket < target) { }
            __threadfence();
        }
        __syncthreads();
    }

    // ---- Phase 2: grid-stride tile loop, 4-deep pipelined TMA stores ----
    int n_tiles = (total_rows + tile_rows - 1) / tile_rows;
    int it = 0;
    for (int tile = blockIdx.x; tile < n_tiles; tile += grid) {
        int tile_base = tile * tile_rows;
        int t = tile_base + threadIdx.x;
        bool full_tile = (tile_base + tile_rows <= total_rows);
        int p = it & 3;

        // Before overwriting buffer p, make sure the bulk group that read it
        // (committed 4 tiles ago) has drained. wait_group 3 = at most 3
        // outstanding -> the oldest (it-4's) is complete.
        if (full_tile && it >= 4) {
            if (threadIdx.x == 0)
                asm volatile("cp.async.bulk.wait_group 3;" ::: "memory");
            __syncthreads();
        }

        if (t < total_rows) {
            int4 idx = __ldcs(&elems[t >> 2]);
            float4 m = __ldcs(&inv[t]);

            float4 v0 = g_conv4[idx.x];
            float4 v1 = g_conv4[idx.y];
            float4 v2 = g_conv4[idx.z];
            float4 v3 = g_conv4[idx.w];

            float r0 = fmaf(m.x, v0.x, fmaf(m.y, v1.x, fmaf(m.z, v2.x, m.w * v3.x)));
            float r1 = fmaf(m.x, v0.y, fmaf(m.y, v1.y, fmaf(m.z, v2.y, m.w * v3.y)));
            float r2 = fmaf(m.x, v0.z, fmaf(m.y, v1.z, fmaf(m.z, v2.z, m.w * v3.z)));

            if (full_tile) {
                // stride-3 word addresses: gcd(3,32)=1 -> conflict-free
                int w = threadIdx.x * 3;
                s_out[p][w + 0] = r0;
                s_out[p][w + 1] = r1;
                s_out[p][w + 2] = r2;
            } else {
                float* o = out + (long)t * 3;
                __stcs(o + 0, r0);
                __stcs(o + 1, r1);
                __stcs(o + 2, r2);
            }
        }

        if (full_tile) {
            asm volatile("fence.proxy.async.shared::cta;" ::: "memory");
            __syncthreads();
            if (threadIdx.x == 0) {
                uint32_t saddr = smem_u32(s_out[p]);
                float* gptr = out + (long)tile_base * 3;   // 3072B-aligned chunk
                asm volatile(
                    "cp.async.bulk.global.shared::cta.bulk_group [%0], [%1], %2;"
                    :: "l"(gptr), "r"(saddr), "r"(tile_rows * 3 * 4) : "memory");
                asm volatile("cp.async.bulk.commit_group;" ::: "memory");
                // NO wait here — lazy drain at buffer reuse / kernel end.
            }
            it++;
        }
    }

    // Final drain.
    if (threadIdx.x == 0)
        asm volatile("cp.async.bulk.wait_group 0;" ::: "memory");
}

extern "C" void kernel_launch(void* const* d_in, const int* in_sizes, int n_in,
                              void* d_out, int out_size)
{
    const float* conv  = (const float*)d_in[0];
    const int4*  elems = (const int4*)d_in[1];
    const float4* inv  = (const float4*)d_in[2];
    float* out = (float*)d_out;

    int n_nodes = in_sizes[0] / 3;
    int E = in_sizes[1] / 4;
    int total_rows = 4 * E;

    // All CTAs must be co-resident for the grid barrier.
    int dev = 0, sms = 0, per_sm = 0;
    cudaGetDevice(&dev);
    cudaDeviceGetAttribute(&sms, cudaDevAttrMultiProcessorCount, dev);
    cudaOccupancyMaxActiveBlocksPerMultiprocessor(&per_sm, fem_fused_kernel, 256, 0);
    if (per_sm < 1) per_sm = 1;
    if (per_sm > 8) per_sm = 8;

    long grid_l = (long)sms * per_sm;
    int n_tiles = (total_rows + 255) / 256;
    if (grid_l > n_tiles) grid_l = n_tiles;
    if (grid_l < 1) grid_l = 1;
    int grid = (int)grid_l;

    fem_fused_kernel<<<grid, 256>>>(conv, elems, inv, out, n_nodes, total_rows);
}

// round 16
// speedup vs baseline: 1.2988x; 1.2988x over previous
#include <cuda_runtime.h>
#include <cstdint>

// convection_vectors: (N_NODES, 3) float32      -> d_in[0]
// mesh_elements:      (E, 4)       int32        -> d_in[1]
// inv_matrices:       (E, 4, 4)    float32      -> d_in[2]
// out:                (E, 4, 3)    float32      -> d_out
//
// out[e,i,c] = sum_j inv[e,i,j] * conv[mesh[e,j], c]

#define MAX_NODES 400000

// Padded gather table: (N, 4) so each vertex is one aligned 16B load. 6.4 MB -> L2-resident.
__device__ float4 g_conv4[MAX_NODES];

__global__ void __launch_bounds__(128)
pad_conv_kernel(const float* __restrict__ conv, int n)
{
    int i = blockIdx.x * blockDim.x + threadIdx.x;
    if (i >= n) return;
    long b = (long)i * 3;
    g_conv4[i] = make_float4(conv[b], conv[b + 1], conv[b + 2], 0.0f);
}

__device__ __forceinline__ uint32_t smem_u32(const void* p)
{
    uint32_t a;
    asm("{ .reg .u64 t; cvta.to.shared.u64 t, %1; cvt.u32.u64 %0, t; }" : "=r"(a) : "l"(p));
    return a;
}

// Verified best (R7/R14): one thread per (element,row) unit; each CTA
// processes TWO consecutive 256-row tiles, double-buffered smem staging
// (conflict-free stride-3 STS) + pipelined 1D TMA bulk stores; single drain
// at CTA end so tile1's compute overlaps tile0's TMA drain.
__global__ void __launch_bounds__(256)
fem_row_tma2_kernel(const int4*   __restrict__ elems,
                    const float4* __restrict__ inv,
                    float*        __restrict__ out,
                    int total_rows)   // 4*E
{
    __shared__ __align__(16) float s_out[2][256 * 3];   // 2 x 3 KB tiles

    const int tile_rows = 256;

#pragma unroll
    for (int it = 0; it < 2; it++) {
        int tile_base = (blockIdx.x * 2 + it) * tile_rows;
        int t = tile_base + threadIdx.x;
        bool full_tile = (tile_base + tile_rows <= total_rows);

        if (t < total_rows) {
            int4 idx = __ldcs(&elems[t >> 2]);
            float4 m = __ldcs(&inv[t]);

            float4 v0 = g_conv4[idx.x];
            float4 v1 = g_conv4[idx.y];
            float4 v2 = g_conv4[idx.z];
            float4 v3 = g_conv4[idx.w];

            float r0 = fmaf(m.x, v0.x, fmaf(m.y, v1.x, fmaf(m.z, v2.x, m.w * v3.x)));
            float r1 = fmaf(m.x, v0.y, fmaf(m.y, v1.y, fmaf(m.z, v2.y, m.w * v3.y)));
            float r2 = fmaf(m.x, v0.z, fmaf(m.y, v1.z, fmaf(m.z, v2.z, m.w * v3.z)));

            if (full_tile) {
                // stride-3 word addresses: gcd(3,32)=1 -> conflict-free
                int w = threadIdx.x * 3;
                s_out[it][w + 0] = r0;
                s_out[it][w + 1] = r1;
                s_out[it][w + 2] = r2;
            } else {
                float* o = out + (long)t * 3;
                __stcs(o + 0, r0);
                __stcs(o + 1, r1);
                __stcs(o + 2, r2);
            }
        }

        if (full_tile) {
            asm volatile("fence.proxy.async.shared::cta;" ::: "memory");
            __syncthreads();
            if (threadIdx.x == 0) {
                uint32_t saddr = smem_u32(s_out[it]);
                float* gptr = out + (long)tile_base * 3;   // 3072B-aligned chunk
                asm volatile(
                    "cp.async.bulk.global.shared::cta.bulk_group [%0], [%1], %2;"
                    :: "l"(gptr), "r"(saddr), "r"(tile_rows * 3 * 4) : "memory");
                asm volatile("cp.async.bulk.commit_group;" ::: "memory");
            }
        }
    }

    // Single drain at CTA end (covers both buffers).
    if (threadIdx.x == 0)
        asm volatile("cp.async.bulk.wait_group 0;" ::: "memory");
}

extern "C" void kernel_launch(void* const* d_in, const int* in_sizes, int n_in,
                              void* d_out, int out_size)
{
    const float* conv  = (const float*)d_in[0];
    const int4*  elems = (const int4*)d_in[1];
    const float4* inv  = (const float4*)d_in[2];
    float* out = (float*)d_out;

    int n_nodes = in_sizes[0] / 3;
    int E = in_sizes[1] / 4;
    int total_rows = 4 * E;

    pad_conv_kernel<<<(n_nodes + 127) / 128, 128>>>(conv, n_nodes);

    int rows_per_cta = 512;   // 2 tiles x 256
    int grid = (total_rows + rows_per_cta - 1) / rows_per_cta;
    fem_row_tma2_kernel<<<grid, 256>>>(elems, inv, out, total_rows);
}